// round 8
// baseline (speedup 1.0000x reference)
#include <cuda_runtime.h>
#include <cuda_fp16.h>
#include <cstdint>

#define T_TOK 8192
#define DIM   1024
#define HID   2048
#define NE    8
#define BM    128
#define BN    128
#define BK    32
#define RCAP  (T_TOK*2 + NE*128)   // 17408 rows = 136 tiles of 128

#define ROWB   80
#define TILEB  (128*ROWB)          // 10240 B
#define STAGEB (4*TILEB)           // Ah, Al, Bh, Bl = 40960 B
#define SMEMSZ (2*STAGEB)          // 81920 B -> 2 CTAs/SM

#define LSCALE 2048.0f
#define INVLS  (1.0f/2048.0f)

// ---------------- device scratch ----------------
__device__ int   g_cnt[NE], g_cur[NE], g_off[NE + 1];
__device__ int   g_tope[T_TOK * 2];
__device__ float g_topp[T_TOK * 2];
__device__ int   g_rowtok[RCAP];
__device__ float g_roww[RCAP];
__device__ __half g_Xh[(size_t)RCAP * DIM];
__device__ __half g_Xl[(size_t)RCAP * DIM];
__device__ __half g_Sh[(size_t)RCAP * HID];
__device__ __half g_Sl[(size_t)RCAP * HID];
__device__ __half g_Wch[(size_t)NE * 2 * HID * DIM];  // [e][2h+p][d]
__device__ __half g_Wcl[(size_t)NE * 2 * HID * DIM];
__device__ __half g_W3h[(size_t)NE * DIM * HID];      // [e][d][h]
__device__ __half g_W3l[(size_t)NE * DIM * HID];

// ---------------- helpers ----------------
__device__ __forceinline__ uint32_t smem_u32(const void* p) {
    uint32_t a;
    asm("{ .reg .u64 t; cvta.to.shared.u64 t, %1; cvt.u32.u64 %0, t; }" : "=r"(a) : "l"(p));
    return a;
}
__device__ __forceinline__ void cp16(uint32_t dst, const void* src) {
    asm volatile("cp.async.cg.shared.global [%0], [%1], 16;" :: "r"(dst), "l"(src));
}
#define CP_COMMIT() asm volatile("cp.async.commit_group;" ::: "memory")
#define CP_WAIT0()  asm volatile("cp.async.wait_group 0;" ::: "memory")

__device__ __forceinline__ void ldsm4(uint32_t* r, uint32_t addr) {
    asm volatile("ldmatrix.sync.aligned.m8n8.x4.shared.b16 {%0,%1,%2,%3}, [%4];"
                 : "=r"(r[0]), "=r"(r[1]), "=r"(r[2]), "=r"(r[3]) : "r"(addr));
}
// f16 inputs, f32 accumulate (main term)
__device__ __forceinline__ void mma_hf32(float* c, const uint32_t* a, uint32_t b0, uint32_t b1) {
    asm volatile("mma.sync.aligned.m16n8k16.row.col.f32.f16.f16.f32 "
                 "{%0,%1,%2,%3}, {%4,%5,%6,%7}, {%8,%9}, {%0,%1,%2,%3};"
                 : "+f"(c[0]), "+f"(c[1]), "+f"(c[2]), "+f"(c[3])
                 : "r"(a[0]), "r"(a[1]), "r"(a[2]), "r"(a[3]), "r"(b0), "r"(b1));
}
// f16 inputs, f16 accumulate (cross terms; 2x rate if HW keeps the classic ratio)
__device__ __forceinline__ void mma_hf16(uint32_t* c, const uint32_t* a, uint32_t b0, uint32_t b1) {
    asm volatile("mma.sync.aligned.m16n8k16.row.col.f16.f16.f16.f16 "
                 "{%0,%1}, {%2,%3,%4,%5}, {%6,%7}, {%0,%1};"
                 : "+r"(c[0]), "+r"(c[1])
                 : "r"(a[0]), "r"(a[1]), "r"(a[2]), "r"(a[3]), "r"(b0), "r"(b1));
}
__device__ __forceinline__ void redg_v2(float* p, float a, float b) {
    asm volatile("red.global.add.v2.f32 [%0], {%1, %2};" :: "l"(p), "f"(a), "f"(b) : "memory");
}
__device__ __forceinline__ float swishf(float a) { return a / (1.0f + __expf(-a)); }
__device__ __forceinline__ void hsplit(float v, __half& h, __half& l) {
    h = __float2half_rn(v);
    l = __float2half_rn((v - __half2float(h)) * LSCALE);
}

// ---------------- routing kernels ----------------
__global__ void k_init() {
    int i = blockIdx.x * blockDim.x + threadIdx.x;
    if (i < NE) { g_cnt[i] = 0; g_cur[i] = 0; }
    if (i < RCAP) g_rowtok[i] = -1;
}

__global__ void k_gate(const float* __restrict__ x, const float* __restrict__ Wg) {
    __shared__ float sWgT[NE * DIM];
    for (int idx = threadIdx.x; idx < DIM * NE; idx += blockDim.x) {
        int d = idx >> 3, e = idx & 7;
        sWgT[e * DIM + d] = Wg[idx];
    }
    __syncthreads();
    int warp = threadIdx.x >> 5, lane = threadIdx.x & 31;
    int t = blockIdx.x * 8 + warp;
    const float* xr = x + (size_t)t * DIM;
    float acc[NE];
#pragma unroll
    for (int e = 0; e < NE; e++) acc[e] = 0.0f;
    for (int d = lane; d < DIM; d += 32) {
        float xv = xr[d];
#pragma unroll
        for (int e = 0; e < NE; e++) acc[e] += xv * sWgT[e * DIM + d];
    }
#pragma unroll
    for (int off = 16; off; off >>= 1)
#pragma unroll
        for (int e = 0; e < NE; e++) acc[e] += __shfl_xor_sync(0xffffffffu, acc[e], off);
    if (lane == 0) {
        int e0 = 0; float v0 = acc[0];
#pragma unroll
        for (int e = 1; e < NE; e++) if (acc[e] > v0) { v0 = acc[e]; e0 = e; }
        int e1 = -1; float v1 = -1e30f;
#pragma unroll
        for (int e = 0; e < NE; e++) if (e != e0 && acc[e] > v1) { v1 = acc[e]; e1 = e; }
        float ex = __expf(v1 - v0);
        g_tope[t * 2 + 0] = e0; g_topp[t * 2 + 0] = 1.0f / (1.0f + ex);
        g_tope[t * 2 + 1] = e1; g_topp[t * 2 + 1] = ex / (1.0f + ex);
        atomicAdd(&g_cnt[e0], 1);
        atomicAdd(&g_cnt[e1], 1);
    }
}

__global__ void k_offsets() {
    if (threadIdx.x == 0) {
        int o = 0;
#pragma unroll
        for (int e = 0; e < NE; e++) {
            g_off[e] = o;
            o += ((g_cnt[e] + 127) / 128) * 128;
        }
        g_off[NE] = o;
    }
}

__global__ void k_scatter() {
    int i = blockIdx.x * blockDim.x + threadIdx.x;
    if (i >= T_TOK * 2) return;
    int e = g_tope[i];
    int pos = g_off[e] + atomicAdd(&g_cur[e], 1);
    g_rowtok[pos] = i >> 1;
    g_roww[pos] = g_topp[i];
}

__global__ void k_gather(const float* __restrict__ x) {
    int r = blockIdx.x;
    int t = g_rowtok[r];
    int i = threadIdx.x;
    float4 v = make_float4(0.f, 0.f, 0.f, 0.f);
    if (t >= 0) v = ((const float4*)(x + (size_t)t * DIM))[i];
    __half h[4], l[4];
    hsplit(v.x, h[0], l[0]); hsplit(v.y, h[1], l[1]);
    hsplit(v.z, h[2], l[2]); hsplit(v.w, h[3], l[3]);
    size_t off = (size_t)r * DIM + i * 4;
    *(ushort4*)(g_Xh + off) = make_ushort4(*(unsigned short*)&h[0], *(unsigned short*)&h[1],
                                           *(unsigned short*)&h[2], *(unsigned short*)&h[3]);
    *(ushort4*)(g_Xl + off) = make_ushort4(*(unsigned short*)&l[0], *(unsigned short*)&l[1],
                                           *(unsigned short*)&l[2], *(unsigned short*)&l[3]);
}

// W1/W2 [e][d][h] -> Wc [e][2h+p][d] (fp16 h/l), interleaved columns
__global__ void k_tr12(const float* __restrict__ src, int p) {
    __shared__ float t[32][33];
    int e = blockIdx.z;
    const float* s = src + (size_t)e * DIM * HID;
    int h0 = blockIdx.x * 32, d0 = blockIdx.y * 32;
    int tx = threadIdx.x, ty = threadIdx.y;
#pragma unroll
    for (int i = ty; i < 32; i += 8)
        t[i][tx] = s[(size_t)(d0 + i) * HID + h0 + tx];
    __syncthreads();
#pragma unroll
    for (int i = ty; i < 32; i += 8) {
        float v = t[tx][i];
        int n = 2 * (h0 + i) + p;
        __half h, l; hsplit(v, h, l);
        size_t off = ((size_t)e * 2 * HID + n) * DIM + d0 + tx;
        g_Wch[off] = h; g_Wcl[off] = l;
    }
}

// W3 [e][h][d] -> W3T [e][d][h] (fp16 h/l)
__global__ void k_tr3(const float* __restrict__ src) {
    __shared__ float t[32][33];
    int e = blockIdx.z;
    const float* s = src + (size_t)e * HID * DIM;
    int d0 = blockIdx.x * 32, h0 = blockIdx.y * 32;
    int tx = threadIdx.x, ty = threadIdx.y;
#pragma unroll
    for (int i = ty; i < 32; i += 8)
        t[i][tx] = s[(size_t)(h0 + i) * DIM + d0 + tx];
    __syncthreads();
#pragma unroll
    for (int i = ty; i < 32; i += 8) {
        float v = t[tx][i];
        __half h, l; hsplit(v, h, l);
        size_t off = ((size_t)e * DIM + d0 + i) * HID + h0 + tx;
        g_W3h[off] = h; g_W3l[off] = l;
    }
}

// ---------------- stage loader: 128 threads, 16 cp16 each ----------------
__device__ __forceinline__ void load_stage(
    uint32_t st, int tid, int k0, int kstride,
    const __half* Ah, const __half* Al, const __half* Bh, const __half* Bl)
{
#pragma unroll
    for (int rep = 0; rep < 4; rep++) {
        int c = tid + rep * 128;
        int row = c >> 2, kc = c & 3;
        uint32_t doff = row * ROWB + kc * 16;
        size_t goff = (size_t)row * kstride + k0 + kc * 8;
        cp16(st + doff,             Ah + goff);
        cp16(st + TILEB + doff,     Al + goff);
        cp16(st + 2 * TILEB + doff, Bh + goff);
        cp16(st + 3 * TILEB + doff, Bl + goff);
    }
    CP_COMMIT();
}

// compute one BK=32 stage, warptile 64x64
// main term -> f32 acc; both cross terms -> shared f16 acc (x2048 prescale)
__device__ __forceinline__ void compute_stage(
    uint32_t st, int warpM, int warpN, int lane,
    float acc[4][8][4], uint32_t acc16[4][8][2])
{
    int mlane = lane & 7;
    int mid = lane >> 3;
#pragma unroll
    for (int ks = 0; ks < 2; ks++) {
        // all B fragments resident (32 regs)
        uint32_t bh[4][4], bl[4][4];
#pragma unroll
        for (int nj = 0; nj < 4; nj++) {
            int row = warpN * 64 + nj * 16 + ((mid >> 1) << 3) + mlane;
            int colB = ks * 32 + ((mid & 1) << 4);
            ldsm4(bh[nj], st + 2 * TILEB + row * ROWB + colB);
            ldsm4(bl[nj], st + 3 * TILEB + row * ROWB + colB);
        }
        // stream A fragments per mi
#pragma unroll
        for (int mi = 0; mi < 4; mi++) {
            uint32_t ah[4], al[4];
            int row = warpM * 64 + mi * 16 + ((mid & 1) << 3) + mlane;
            int colB = ks * 32 + ((mid >> 1) << 4);
            ldsm4(ah, st + row * ROWB + colB);
            ldsm4(al, st + TILEB + row * ROWB + colB);
#pragma unroll
            for (int nj = 0; nj < 4; nj++)
#pragma unroll
                for (int tt = 0; tt < 2; tt++) {
                    int ni = nj * 2 + tt;
                    mma_hf32(acc[mi][ni], ah, bh[nj][tt * 2], bh[nj][tt * 2 + 1]);
                    mma_hf16(acc16[mi][ni], ah, bl[nj][tt * 2], bl[nj][tt * 2 + 1]);
                    mma_hf16(acc16[mi][ni], al, bh[nj][tt * 2], bh[nj][tt * 2 + 1]);
                }
        }
    }
}

#define GEMM_MAINLOOP(NC, KSTRIDE)                                                  \
    load_stage(sb, tid, 0, KSTRIDE, Ah, Al, Bh, Bl);                                \
    for (int c = 0; c < (NC); c++) {                                                \
        CP_WAIT0();                                                                 \
        __syncthreads();                                                            \
        if (c + 1 < (NC))                                                           \
            load_stage(sb + ((c + 1) & 1) * STAGEB, tid, (c + 1) * BK, KSTRIDE,     \
                       Ah, Al, Bh, Bl);                                             \
        compute_stage(sb + (c & 1) * STAGEB, warpM, warpN, lane, acc, acc16);       \
    }

// combine acc32 + acc16/2048 at one (mi, ni)
__device__ __forceinline__ void combine4(const float* a32, const uint32_t* a16, float* o) {
    __half2 x01 = *(const __half2*)&a16[0];
    __half2 x23 = *(const __half2*)&a16[1];
    o[0] = a32[0] + __half2float(x01.x) * INVLS;
    o[1] = a32[1] + __half2float(x01.y) * INVLS;
    o[2] = a32[2] + __half2float(x23.x) * INVLS;
    o[3] = a32[3] + __half2float(x23.y) * INVLS;
}

// ---------------- GEMM1: [RCAP,4096] = X @ Wc, epilogue SwiGLU -> Sh/Sl ----------------
__global__ __launch_bounds__(128, 2) void k_gemm1() {
    int row0 = blockIdx.y * BM;
    int e = 0;
#pragma unroll
    for (int i = 1; i < NE; i++) if (g_off[i] <= row0) e = i;
    if (g_cnt[e] - (row0 - g_off[e]) <= 0) return;

    extern __shared__ __align__(128) char smem[];
    uint32_t sb = smem_u32(smem);
    int tid = threadIdx.x, wid = tid >> 5, lane = tid & 31;
    int warpM = wid >> 1, warpN = wid & 1;
    int n0 = blockIdx.x * BN;

    const __half* Ah = g_Xh + (size_t)row0 * DIM;
    const __half* Al = g_Xl + (size_t)row0 * DIM;
    const __half* Bh = g_Wch + (size_t)e * 2 * HID * DIM + (size_t)n0 * DIM;
    const __half* Bl = g_Wcl + (size_t)e * 2 * HID * DIM + (size_t)n0 * DIM;

    float acc[4][8][4];
    uint32_t acc16[4][8][2];
#pragma unroll
    for (int a = 0; a < 4; a++)
#pragma unroll
        for (int b = 0; b < 8; b++) {
#pragma unroll
            for (int c = 0; c < 4; c++) acc[a][b][c] = 0.0f;
            acc16[a][b][0] = 0u; acc16[a][b][1] = 0u;
        }

    GEMM_MAINLOOP(DIM / BK, DIM)

    // epilogue: combine, SwiGLU, stage fp16 h/l through smem, 16B stores
    __syncthreads();
    char* stg = smem + wid * 4096;
    int qrow = lane >> 2, qcol = lane & 3;
    int jgb = (n0 >> 1) + warpN * 32;
#pragma unroll
    for (int mi = 0; mi < 4; mi++) {
        int r0 = row0 + warpM * 64 + mi * 16;
#pragma unroll
        for (int ni = 0; ni < 8; ni++) {
            int col = ni * 4 + qcol;
            float v[4];
            combine4(acc[mi][ni], acc16[mi][ni], v);
            float v0 = swishf(v[0]) * v[1];
            float v1 = swishf(v[2]) * v[3];
            __half h, l;
            hsplit(v0, h, l);
            *(__half*)(stg + qrow * 80 + col * 2) = h;
            *(__half*)(stg + 2048 + qrow * 80 + col * 2) = l;
            hsplit(v1, h, l);
            *(__half*)(stg + (qrow + 8) * 80 + col * 2) = h;
            *(__half*)(stg + 2048 + (qrow + 8) * 80 + col * 2) = l;
        }
        __syncwarp();
#pragma unroll
        for (int k = 0; k < 2; k++) {
            int chunk = lane + 32 * k;
            int row = chunk >> 2, part = chunk & 3;
            uint4 vh = *(uint4*)(stg + row * 80 + part * 16);
            uint4 vl = *(uint4*)(stg + 2048 + row * 80 + part * 16);
            size_t o = (size_t)(r0 + row) * HID + jgb + part * 8;
            *(uint4*)(g_Sh + o) = vh;
            *(uint4*)(g_Sl + o) = vl;
        }
        __syncwarp();
    }
}

// ---------------- GEMM2: out[t] += w * (S @ W3T) ----------------
__global__ __launch_bounds__(128, 2) void k_gemm2(float* __restrict__ out) {
    int row0 = blockIdx.y * BM;
    int e = 0;
#pragma unroll
    for (int i = 1; i < NE; i++) if (g_off[i] <= row0) e = i;
    if (g_cnt[e] - (row0 - g_off[e]) <= 0) return;

    extern __shared__ __align__(128) char smem[];
    uint32_t sb = smem_u32(smem);
    int tid = threadIdx.x, wid = tid >> 5, lane = tid & 31;
    int warpM = wid >> 1, warpN = wid & 1;
    int n0 = blockIdx.x * BN;

    const __half* Ah = g_Sh + (size_t)row0 * HID;
    const __half* Al = g_Sl + (size_t)row0 * HID;
    const __half* Bh = g_W3h + (size_t)e * DIM * HID + (size_t)n0 * HID;
    const __half* Bl = g_W3l + (size_t)e * DIM * HID + (size_t)n0 * HID;

    float acc[4][8][4];
    uint32_t acc16[4][8][2];
#pragma unroll
    for (int a = 0; a < 4; a++)
#pragma unroll
        for (int b = 0; b < 8; b++) {
#pragma unroll
            for (int c = 0; c < 4; c++) acc[a][b][c] = 0.0f;
            acc16[a][b][0] = 0u; acc16[a][b][1] = 0u;
        }

    GEMM_MAINLOOP(HID / BK, HID)

    int qrow = lane >> 2, qcol = lane & 3;
#pragma unroll
    for (int mi = 0; mi < 4; mi++) {
        int rbase = row0 + warpM * 64 + mi * 16 + qrow;
#pragma unroll
        for (int ni = 0; ni < 8; ni++) {
            float v[4];
            combine4(acc[mi][ni], acc16[mi][ni], v);
            int colg = n0 + warpN * 64 + ni * 8 + qcol * 2;
#pragma unroll
            for (int half = 0; half < 2; half++) {
                int r = rbase + half * 8;
                int t = g_rowtok[r];
                if (t < 0) continue;
                float wgt = g_roww[r];
                float* orow = out + (size_t)t * DIM;
                redg_v2(orow + colg, wgt * v[half * 2], wgt * v[half * 2 + 1]);
            }
        }
    }
}

// ---------------- launch ----------------
extern "C" void kernel_launch(void* const* d_in, const int* in_sizes, int n_in,
                              void* d_out, int out_size) {
    const float* x  = (const float*)d_in[0];
    const float* Wg = (const float*)d_in[1];
    const float* W1 = (const float*)d_in[2];
    const float* W2 = (const float*)d_in[3];
    const float* W3 = (const float*)d_in[4];
    float* out = (float*)d_out;

    cudaFuncSetAttribute(k_gemm1, cudaFuncAttributeMaxDynamicSharedMemorySize, SMEMSZ);
    cudaFuncSetAttribute(k_gemm2, cudaFuncAttributeMaxDynamicSharedMemorySize, SMEMSZ);

    cudaMemsetAsync(out, 0, (size_t)T_TOK * DIM * sizeof(float));
    k_init<<<(RCAP + 255) / 256, 256>>>();
    k_gate<<<T_TOK / 8, 256>>>(x, Wg);
    k_offsets<<<1, 32>>>();
    k_scatter<<<(T_TOK * 2 + 255) / 256, 256>>>();
    k_gather<<<RCAP, 256>>>(x);
    k_tr12<<<dim3(HID / 32, DIM / 32, NE), dim3(32, 8)>>>(W1, 0);
    k_tr12<<<dim3(HID / 32, DIM / 32, NE), dim3(32, 8)>>>(W2, 1);
    k_tr3<<<dim3(DIM / 32, HID / 32, NE), dim3(32, 8)>>>(W3);

    k_gemm1<<<dim3(2 * HID / BN, RCAP / BM), 128, SMEMSZ>>>();
    k_gemm2<<<dim3(DIM / BN, RCAP / BM), 128, SMEMSZ>>>(out);
}

// round 9
// speedup vs baseline: 1.4144x; 1.4144x over previous
#include <cuda_runtime.h>
#include <cuda_fp16.h>
#include <cstdint>

#define T_TOK 8192
#define DIM   1024
#define HID   2048
#define NE    8
#define BM    128
#define BN    128
#define BK    32
#define RCAP  (T_TOK*2 + NE*128)   // 17408 rows = 136 tiles of 128

#define ROWB   80
#define TILEB  (128*ROWB)          // 10240 B
#define STAGEB (3*TILEB)           // Ah, Al, B = 30720 B
#define SMEMSZ (2*STAGEB)          // 61440 B -> 2 CTAs/SM

// ---------------- device scratch ----------------
__device__ int   g_cnt[NE], g_cur[NE], g_off[NE + 1];
__device__ int   g_tope[T_TOK * 2];
__device__ float g_topp[T_TOK * 2];
__device__ int   g_rowtok[RCAP];
__device__ float g_roww[RCAP];
__device__ __half g_Xh[(size_t)RCAP * DIM];
__device__ __half g_Xl[(size_t)RCAP * DIM];
__device__ __half g_Sh[(size_t)RCAP * HID];
__device__ __half g_Sl[(size_t)RCAP * HID];
__device__ __half g_Wc[(size_t)NE * 2 * HID * DIM];   // [e][2h+p][d], single fp16
__device__ __half g_W3[(size_t)NE * DIM * HID];       // [e][d][h],   single fp16

// ---------------- helpers ----------------
__device__ __forceinline__ uint32_t smem_u32(const void* p) {
    uint32_t a;
    asm("{ .reg .u64 t; cvta.to.shared.u64 t, %1; cvt.u32.u64 %0, t; }" : "=r"(a) : "l"(p));
    return a;
}
__device__ __forceinline__ void cp16(uint32_t dst, const void* src) {
    asm volatile("cp.async.cg.shared.global [%0], [%1], 16;" :: "r"(dst), "l"(src));
}
#define CP_COMMIT() asm volatile("cp.async.commit_group;" ::: "memory")
#define CP_WAIT0()  asm volatile("cp.async.wait_group 0;" ::: "memory")

__device__ __forceinline__ void ldsm4(uint32_t* r, uint32_t addr) {
    asm volatile("ldmatrix.sync.aligned.m8n8.x4.shared.b16 {%0,%1,%2,%3}, [%4];"
                 : "=r"(r[0]), "=r"(r[1]), "=r"(r[2]), "=r"(r[3]) : "r"(addr));
}
__device__ __forceinline__ void mma_hf32(float* c, const uint32_t* a, uint32_t b0, uint32_t b1) {
    asm volatile("mma.sync.aligned.m16n8k16.row.col.f32.f16.f16.f32 "
                 "{%0,%1,%2,%3}, {%4,%5,%6,%7}, {%8,%9}, {%0,%1,%2,%3};"
                 : "+f"(c[0]), "+f"(c[1]), "+f"(c[2]), "+f"(c[3])
                 : "r"(a[0]), "r"(a[1]), "r"(a[2]), "r"(a[3]), "r"(b0), "r"(b1));
}
__device__ __forceinline__ void redg_v2(float* p, float a, float b) {
    asm volatile("red.global.add.v2.f32 [%0], {%1, %2};" :: "l"(p), "f"(a), "f"(b) : "memory");
}
__device__ __forceinline__ float swishf(float a) { return a / (1.0f + __expf(-a)); }
__device__ __forceinline__ void hsplit(float v, __half& h, __half& l) {
    h = __float2half_rn(v);
    l = __float2half_rn(v - __half2float(h));
}

// ---------------- routing kernels ----------------
__global__ void k_init() {
    int i = blockIdx.x * blockDim.x + threadIdx.x;
    if (i < NE) { g_cnt[i] = 0; g_cur[i] = 0; }
    if (i < RCAP) g_rowtok[i] = -1;
}

__global__ void k_gate(const float* __restrict__ x, const float* __restrict__ Wg) {
    __shared__ float sWgT[NE * DIM];
    for (int idx = threadIdx.x; idx < DIM * NE; idx += blockDim.x) {
        int d = idx >> 3, e = idx & 7;
        sWgT[e * DIM + d] = Wg[idx];
    }
    __syncthreads();
    int warp = threadIdx.x >> 5, lane = threadIdx.x & 31;
    int t = blockIdx.x * 8 + warp;
    const float* xr = x + (size_t)t * DIM;
    float acc[NE];
#pragma unroll
    for (int e = 0; e < NE; e++) acc[e] = 0.0f;
    for (int d = lane; d < DIM; d += 32) {
        float xv = xr[d];
#pragma unroll
        for (int e = 0; e < NE; e++) acc[e] += xv * sWgT[e * DIM + d];
    }
#pragma unroll
    for (int off = 16; off; off >>= 1)
#pragma unroll
        for (int e = 0; e < NE; e++) acc[e] += __shfl_xor_sync(0xffffffffu, acc[e], off);
    if (lane == 0) {
        int e0 = 0; float v0 = acc[0];
#pragma unroll
        for (int e = 1; e < NE; e++) if (acc[e] > v0) { v0 = acc[e]; e0 = e; }
        int e1 = -1; float v1 = -1e30f;
#pragma unroll
        for (int e = 0; e < NE; e++) if (e != e0 && acc[e] > v1) { v1 = acc[e]; e1 = e; }
        float ex = __expf(v1 - v0);
        g_tope[t * 2 + 0] = e0; g_topp[t * 2 + 0] = 1.0f / (1.0f + ex);
        g_tope[t * 2 + 1] = e1; g_topp[t * 2 + 1] = ex / (1.0f + ex);
        atomicAdd(&g_cnt[e0], 1);
        atomicAdd(&g_cnt[e1], 1);
    }
}

__global__ void k_offsets() {
    if (threadIdx.x == 0) {
        int o = 0;
#pragma unroll
        for (int e = 0; e < NE; e++) {
            g_off[e] = o;
            o += ((g_cnt[e] + 127) / 128) * 128;
        }
        g_off[NE] = o;
    }
}

__global__ void k_scatter() {
    int i = blockIdx.x * blockDim.x + threadIdx.x;
    if (i >= T_TOK * 2) return;
    int e = g_tope[i];
    int pos = g_off[e] + atomicAdd(&g_cur[e], 1);
    g_rowtok[pos] = i >> 1;
    g_roww[pos] = g_topp[i];
}

__global__ void k_gather(const float* __restrict__ x) {
    int r = blockIdx.x;
    int t = g_rowtok[r];
    int i = threadIdx.x;
    float4 v = make_float4(0.f, 0.f, 0.f, 0.f);
    if (t >= 0) v = ((const float4*)(x + (size_t)t * DIM))[i];
    __half h[4], l[4];
    hsplit(v.x, h[0], l[0]); hsplit(v.y, h[1], l[1]);
    hsplit(v.z, h[2], l[2]); hsplit(v.w, h[3], l[3]);
    size_t off = (size_t)r * DIM + i * 4;
    *(ushort4*)(g_Xh + off) = make_ushort4(*(unsigned short*)&h[0], *(unsigned short*)&h[1],
                                           *(unsigned short*)&h[2], *(unsigned short*)&h[3]);
    *(ushort4*)(g_Xl + off) = make_ushort4(*(unsigned short*)&l[0], *(unsigned short*)&l[1],
                                           *(unsigned short*)&l[2], *(unsigned short*)&l[3]);
}

// W1/W2 [e][d][h] -> Wc [e][2h+p][d] (single fp16), interleaved columns
__global__ void k_tr12(const float* __restrict__ src, int p) {
    __shared__ float t[32][33];
    int e = blockIdx.z;
    const float* s = src + (size_t)e * DIM * HID;
    int h0 = blockIdx.x * 32, d0 = blockIdx.y * 32;
    int tx = threadIdx.x, ty = threadIdx.y;
#pragma unroll
    for (int i = ty; i < 32; i += 8)
        t[i][tx] = s[(size_t)(d0 + i) * HID + h0 + tx];
    __syncthreads();
#pragma unroll
    for (int i = ty; i < 32; i += 8) {
        float v = t[tx][i];
        int n = 2 * (h0 + i) + p;
        g_Wc[((size_t)e * 2 * HID + n) * DIM + d0 + tx] = __float2half_rn(v);
    }
}

// W3 [e][h][d] -> W3T [e][d][h] (single fp16)
__global__ void k_tr3(const float* __restrict__ src) {
    __shared__ float t[32][33];
    int e = blockIdx.z;
    const float* s = src + (size_t)e * HID * DIM;
    int d0 = blockIdx.x * 32, h0 = blockIdx.y * 32;
    int tx = threadIdx.x, ty = threadIdx.y;
#pragma unroll
    for (int i = ty; i < 32; i += 8)
        t[i][tx] = s[(size_t)(h0 + i) * DIM + d0 + tx];
    __syncthreads();
#pragma unroll
    for (int i = ty; i < 32; i += 8) {
        float v = t[tx][i];
        g_W3[((size_t)e * DIM + d0 + i) * HID + h0 + tx] = __float2half_rn(v);
    }
}

// ---------------- stage loader: 128 threads, 12 cp16 each ----------------
__device__ __forceinline__ void load_stage(
    uint32_t st, int tid, int k0, int kstride,
    const __half* Ah, const __half* Al, const __half* B)
{
#pragma unroll
    for (int rep = 0; rep < 4; rep++) {
        int c = tid + rep * 128;
        int row = c >> 2, kc = c & 3;
        uint32_t doff = row * ROWB + kc * 16;
        size_t goff = (size_t)row * kstride + k0 + kc * 8;
        cp16(st + doff,             Ah + goff);
        cp16(st + TILEB + doff,     Al + goff);
        cp16(st + 2 * TILEB + doff, B + goff);
    }
    CP_COMMIT();
}

// compute one BK=32 stage, warptile 64x64: (Ah + Al) @ B, shared f32 acc
__device__ __forceinline__ void compute_stage(
    uint32_t st, int warpM, int warpN, int lane, float acc[4][8][4])
{
    int mlane = lane & 7;
    int mid = lane >> 3;
#pragma unroll
    for (int ks = 0; ks < 2; ks++) {
        uint32_t b[4][4];
#pragma unroll
        for (int nj = 0; nj < 4; nj++) {
            int row = warpN * 64 + nj * 16 + ((mid >> 1) << 3) + mlane;
            int colB = ks * 32 + ((mid & 1) << 4);
            ldsm4(b[nj], st + 2 * TILEB + row * ROWB + colB);
        }
#pragma unroll
        for (int mi = 0; mi < 4; mi++) {
            uint32_t ah[4], al[4];
            int row = warpM * 64 + mi * 16 + ((mid & 1) << 3) + mlane;
            int colB = ks * 32 + ((mid >> 1) << 4);
            ldsm4(ah, st + row * ROWB + colB);
            ldsm4(al, st + TILEB + row * ROWB + colB);
#pragma unroll
            for (int nj = 0; nj < 4; nj++)
#pragma unroll
                for (int tt = 0; tt < 2; tt++) {
                    int ni = nj * 2 + tt;
                    mma_hf32(acc[mi][ni], ah, b[nj][tt * 2], b[nj][tt * 2 + 1]);
                    mma_hf32(acc[mi][ni], al, b[nj][tt * 2], b[nj][tt * 2 + 1]);
                }
        }
    }
}

#define GEMM_MAINLOOP(NC, KSTRIDE)                                                  \
    load_stage(sb, tid, 0, KSTRIDE, Ah, Al, Bp);                                    \
    for (int c = 0; c < (NC); c++) {                                                \
        CP_WAIT0();                                                                 \
        __syncthreads();                                                            \
        if (c + 1 < (NC))                                                           \
            load_stage(sb + ((c + 1) & 1) * STAGEB, tid, (c + 1) * BK, KSTRIDE,     \
                       Ah, Al, Bp);                                                 \
        compute_stage(sb + (c & 1) * STAGEB, warpM, warpN, lane, acc);              \
    }

// ---------------- GEMM1: [RCAP,4096] = X @ Wc, epilogue SwiGLU -> Sh/Sl ----------------
__global__ __launch_bounds__(128, 2) void k_gemm1() {
    int row0 = blockIdx.y * BM;
    int e = 0;
#pragma unroll
    for (int i = 1; i < NE; i++) if (g_off[i] <= row0) e = i;
    if (g_cnt[e] - (row0 - g_off[e]) <= 0) return;

    extern __shared__ __align__(128) char smem[];
    uint32_t sb = smem_u32(smem);
    int tid = threadIdx.x, wid = tid >> 5, lane = tid & 31;
    int warpM = wid >> 1, warpN = wid & 1;
    int n0 = blockIdx.x * BN;

    const __half* Ah = g_Xh + (size_t)row0 * DIM;
    const __half* Al = g_Xl + (size_t)row0 * DIM;
    const __half* Bp = g_Wc + (size_t)e * 2 * HID * DIM + (size_t)n0 * DIM;

    float acc[4][8][4];
#pragma unroll
    for (int a = 0; a < 4; a++)
#pragma unroll
        for (int b = 0; b < 8; b++)
#pragma unroll
            for (int c = 0; c < 4; c++) acc[a][b][c] = 0.0f;

    GEMM_MAINLOOP(DIM / BK, DIM)

    // epilogue: SwiGLU, stage fp16 h/l through smem, coalesced 16B stores
    __syncthreads();
    char* stg = smem + wid * 4096;
    int qrow = lane >> 2, qcol = lane & 3;
    int jgb = (n0 >> 1) + warpN * 32;
#pragma unroll
    for (int mi = 0; mi < 4; mi++) {
        int r0 = row0 + warpM * 64 + mi * 16;
#pragma unroll
        for (int ni = 0; ni < 8; ni++) {
            int col = ni * 4 + qcol;
            float v0 = swishf(acc[mi][ni][0]) * acc[mi][ni][1];
            float v1 = swishf(acc[mi][ni][2]) * acc[mi][ni][3];
            __half h, l;
            hsplit(v0, h, l);
            *(__half*)(stg + qrow * 80 + col * 2) = h;
            *(__half*)(stg + 2048 + qrow * 80 + col * 2) = l;
            hsplit(v1, h, l);
            *(__half*)(stg + (qrow + 8) * 80 + col * 2) = h;
            *(__half*)(stg + 2048 + (qrow + 8) * 80 + col * 2) = l;
        }
        __syncwarp();
#pragma unroll
        for (int k = 0; k < 2; k++) {
            int chunk = lane + 32 * k;
            int row = chunk >> 2, part = chunk & 3;
            uint4 vh = *(uint4*)(stg + row * 80 + part * 16);
            uint4 vl = *(uint4*)(stg + 2048 + row * 80 + part * 16);
            size_t o = (size_t)(r0 + row) * HID + jgb + part * 8;
            *(uint4*)(g_Sh + o) = vh;
            *(uint4*)(g_Sl + o) = vl;
        }
        __syncwarp();
    }
}

// ---------------- GEMM2: out[t] += w * (S @ W3T) ----------------
__global__ __launch_bounds__(128, 2) void k_gemm2(float* __restrict__ out) {
    int row0 = blockIdx.y * BM;
    int e = 0;
#pragma unroll
    for (int i = 1; i < NE; i++) if (g_off[i] <= row0) e = i;
    if (g_cnt[e] - (row0 - g_off[e]) <= 0) return;

    extern __shared__ __align__(128) char smem[];
    uint32_t sb = smem_u32(smem);
    int tid = threadIdx.x, wid = tid >> 5, lane = tid & 31;
    int warpM = wid >> 1, warpN = wid & 1;
    int n0 = blockIdx.x * BN;

    const __half* Ah = g_Sh + (size_t)row0 * HID;
    const __half* Al = g_Sl + (size_t)row0 * HID;
    const __half* Bp = g_W3 + (size_t)e * DIM * HID + (size_t)n0 * HID;

    float acc[4][8][4];
#pragma unroll
    for (int a = 0; a < 4; a++)
#pragma unroll
        for (int b = 0; b < 8; b++)
#pragma unroll
            for (int c = 0; c < 4; c++) acc[a][b][c] = 0.0f;

    GEMM_MAINLOOP(HID / BK, HID)

    int qrow = lane >> 2, qcol = lane & 3;
#pragma unroll
    for (int mi = 0; mi < 4; mi++) {
        int rbase = row0 + warpM * 64 + mi * 16 + qrow;
#pragma unroll
        for (int half = 0; half < 2; half++) {
            int r = rbase + half * 8;
            int t = g_rowtok[r];
            if (t < 0) continue;
            float wgt = g_roww[r];
            float* orow = out + (size_t)t * DIM;
#pragma unroll
            for (int ni = 0; ni < 8; ni++) {
                int colg = n0 + warpN * 64 + ni * 8 + qcol * 2;
                redg_v2(orow + colg, wgt * acc[mi][ni][half * 2],
                                     wgt * acc[mi][ni][half * 2 + 1]);
            }
        }
    }
}

// ---------------- launch ----------------
extern "C" void kernel_launch(void* const* d_in, const int* in_sizes, int n_in,
                              void* d_out, int out_size) {
    const float* x  = (const float*)d_in[0];
    const float* Wg = (const float*)d_in[1];
    const float* W1 = (const float*)d_in[2];
    const float* W2 = (const float*)d_in[3];
    const float* W3 = (const float*)d_in[4];
    float* out = (float*)d_out;

    cudaFuncSetAttribute(k_gemm1, cudaFuncAttributeMaxDynamicSharedMemorySize, SMEMSZ);
    cudaFuncSetAttribute(k_gemm2, cudaFuncAttributeMaxDynamicSharedMemorySize, SMEMSZ);

    cudaMemsetAsync(out, 0, (size_t)T_TOK * DIM * sizeof(float));
    k_init<<<(RCAP + 255) / 256, 256>>>();
    k_gate<<<T_TOK / 8, 256>>>(x, Wg);
    k_offsets<<<1, 32>>>();
    k_scatter<<<(T_TOK * 2 + 255) / 256, 256>>>();
    k_gather<<<RCAP, 256>>>(x);
    k_tr12<<<dim3(HID / 32, DIM / 32, NE), dim3(32, 8)>>>(W1, 0);
    k_tr12<<<dim3(HID / 32, DIM / 32, NE), dim3(32, 8)>>>(W2, 1);
    k_tr3<<<dim3(DIM / 32, HID / 32, NE), dim3(32, 8)>>>(W3);

    k_gemm1<<<dim3(2 * HID / BN, RCAP / BM), 128, SMEMSZ>>>();
    k_gemm2<<<dim3(DIM / BN, RCAP / BM), 128, SMEMSZ>>>(out);
}

// round 10
// speedup vs baseline: 1.6062x; 1.1356x over previous
#include <cuda_runtime.h>
#include <cuda_fp16.h>
#include <cstdint>

#define T_TOK 8192
#define DIM   1024
#define HID   2048
#define NE    8
#define BM    128
#define BN    128
#define BK    32
#define RCAP  (T_TOK*2 + NE*128)   // 17408 rows = 136 tiles of 128

#define ROWB    80
#define TILEB   (128*ROWB)          // 10240 B
#define STAGE1B (3*TILEB)           // Ah, Al, B
#define SMEM1SZ (2*STAGE1B)         // 61440
#define STAGE2B (2*TILEB)           // A, B
#define SMEM2SZ (2*STAGE2B)         // 40960

// ---------------- device scratch ----------------
__device__ int   g_cnt[NE], g_cur[NE], g_off[NE + 1];
__device__ int   g_tope[T_TOK * 2];
__device__ float g_topp[T_TOK * 2];
__device__ int   g_rowtok[RCAP];
__device__ float g_roww[RCAP];
__device__ __half g_Xh[(size_t)RCAP * DIM];
__device__ __half g_Xl[(size_t)RCAP * DIM];
__device__ __half g_S [(size_t)RCAP * HID];           // single fp16 now
__device__ __half g_Wc[(size_t)NE * 2 * HID * DIM];   // [e][2h+p][d]
__device__ __half g_W3[(size_t)NE * DIM * HID];       // [e][d][h]

// ---------------- helpers ----------------
__device__ __forceinline__ uint32_t smem_u32(const void* p) {
    uint32_t a;
    asm("{ .reg .u64 t; cvta.to.shared.u64 t, %1; cvt.u32.u64 %0, t; }" : "=r"(a) : "l"(p));
    return a;
}
__device__ __forceinline__ void cp16(uint32_t dst, const void* src) {
    asm volatile("cp.async.cg.shared.global [%0], [%1], 16;" :: "r"(dst), "l"(src));
}
#define CP_COMMIT() asm volatile("cp.async.commit_group;" ::: "memory")
#define CP_WAIT0()  asm volatile("cp.async.wait_group 0;" ::: "memory")

__device__ __forceinline__ void ldsm4(uint32_t* r, uint32_t addr) {
    asm volatile("ldmatrix.sync.aligned.m8n8.x4.shared.b16 {%0,%1,%2,%3}, [%4];"
                 : "=r"(r[0]), "=r"(r[1]), "=r"(r[2]), "=r"(r[3]) : "r"(addr));
}
__device__ __forceinline__ void mma_hf32(float* c, const uint32_t* a, uint32_t b0, uint32_t b1) {
    asm volatile("mma.sync.aligned.m16n8k16.row.col.f32.f16.f16.f32 "
                 "{%0,%1,%2,%3}, {%4,%5,%6,%7}, {%8,%9}, {%0,%1,%2,%3};"
                 : "+f"(c[0]), "+f"(c[1]), "+f"(c[2]), "+f"(c[3])
                 : "r"(a[0]), "r"(a[1]), "r"(a[2]), "r"(a[3]), "r"(b0), "r"(b1));
}
__device__ __forceinline__ void redg_v2(float* p, float a, float b) {
    asm volatile("red.global.add.v2.f32 [%0], {%1, %2};" :: "l"(p), "f"(a), "f"(b) : "memory");
}
__device__ __forceinline__ float swishf(float a) { return a / (1.0f + __expf(-a)); }
__device__ __forceinline__ void hsplit(float v, __half& h, __half& l) {
    h = __float2half_rn(v);
    l = __float2half_rn(v - __half2float(h));
}

// ---------------- routing kernels ----------------
__global__ void k_init() {
    int i = blockIdx.x * blockDim.x + threadIdx.x;
    if (i < NE) { g_cnt[i] = 0; g_cur[i] = 0; }
    if (i < RCAP) g_rowtok[i] = -1;
}

__global__ void k_gate(const float* __restrict__ x, const float* __restrict__ Wg) {
    __shared__ float sWgT[NE * DIM];
    for (int idx = threadIdx.x; idx < DIM * NE; idx += blockDim.x) {
        int d = idx >> 3, e = idx & 7;
        sWgT[e * DIM + d] = Wg[idx];
    }
    __syncthreads();
    int warp = threadIdx.x >> 5, lane = threadIdx.x & 31;
    int t = blockIdx.x * 8 + warp;
    const float* xr = x + (size_t)t * DIM;
    float acc[NE];
#pragma unroll
    for (int e = 0; e < NE; e++) acc[e] = 0.0f;
    for (int d = lane; d < DIM; d += 32) {
        float xv = xr[d];
#pragma unroll
        for (int e = 0; e < NE; e++) acc[e] += xv * sWgT[e * DIM + d];
    }
#pragma unroll
    for (int off = 16; off; off >>= 1)
#pragma unroll
        for (int e = 0; e < NE; e++) acc[e] += __shfl_xor_sync(0xffffffffu, acc[e], off);
    if (lane == 0) {
        int e0 = 0; float v0 = acc[0];
#pragma unroll
        for (int e = 1; e < NE; e++) if (acc[e] > v0) { v0 = acc[e]; e0 = e; }
        int e1 = -1; float v1 = -1e30f;
#pragma unroll
        for (int e = 0; e < NE; e++) if (e != e0 && acc[e] > v1) { v1 = acc[e]; e1 = e; }
        float ex = __expf(v1 - v0);
        g_tope[t * 2 + 0] = e0; g_topp[t * 2 + 0] = 1.0f / (1.0f + ex);
        g_tope[t * 2 + 1] = e1; g_topp[t * 2 + 1] = ex / (1.0f + ex);
        atomicAdd(&g_cnt[e0], 1);
        atomicAdd(&g_cnt[e1], 1);
    }
}

__global__ void k_offsets() {
    if (threadIdx.x == 0) {
        int o = 0;
#pragma unroll
        for (int e = 0; e < NE; e++) {
            g_off[e] = o;
            o += ((g_cnt[e] + 127) / 128) * 128;
        }
        g_off[NE] = o;
    }
}

__global__ void k_scatter() {
    int i = blockIdx.x * blockDim.x + threadIdx.x;
    if (i >= T_TOK * 2) return;
    int e = g_tope[i];
    int pos = g_off[e] + atomicAdd(&g_cur[e], 1);
    g_rowtok[pos] = i >> 1;
    g_roww[pos] = g_topp[i];
}

__global__ void k_gather(const float* __restrict__ x) {
    int r = blockIdx.x;
    int t = g_rowtok[r];
    int i = threadIdx.x;
    float4 v = make_float4(0.f, 0.f, 0.f, 0.f);
    if (t >= 0) v = ((const float4*)(x + (size_t)t * DIM))[i];
    __half h[4], l[4];
    hsplit(v.x, h[0], l[0]); hsplit(v.y, h[1], l[1]);
    hsplit(v.z, h[2], l[2]); hsplit(v.w, h[3], l[3]);
    size_t off = (size_t)r * DIM + i * 4;
    *(ushort4*)(g_Xh + off) = make_ushort4(*(unsigned short*)&h[0], *(unsigned short*)&h[1],
                                           *(unsigned short*)&h[2], *(unsigned short*)&h[3]);
    *(ushort4*)(g_Xl + off) = make_ushort4(*(unsigned short*)&l[0], *(unsigned short*)&l[1],
                                           *(unsigned short*)&l[2], *(unsigned short*)&l[3]);
}

// W1/W2 [e][d][h] -> Wc [e][2h+p][d] (single fp16), interleaved columns
__global__ void k_tr12(const float* __restrict__ src, int p) {
    __shared__ float t[32][33];
    int e = blockIdx.z;
    const float* s = src + (size_t)e * DIM * HID;
    int h0 = blockIdx.x * 32, d0 = blockIdx.y * 32;
    int tx = threadIdx.x, ty = threadIdx.y;
#pragma unroll
    for (int i = ty; i < 32; i += 8)
        t[i][tx] = s[(size_t)(d0 + i) * HID + h0 + tx];
    __syncthreads();
#pragma unroll
    for (int i = ty; i < 32; i += 8) {
        float v = t[tx][i];
        int n = 2 * (h0 + i) + p;
        g_Wc[((size_t)e * 2 * HID + n) * DIM + d0 + tx] = __float2half_rn(v);
    }
}

// W3 [e][h][d] -> W3T [e][d][h] (single fp16)
__global__ void k_tr3(const float* __restrict__ src) {
    __shared__ float t[32][33];
    int e = blockIdx.z;
    const float* s = src + (size_t)e * HID * DIM;
    int d0 = blockIdx.x * 32, h0 = blockIdx.y * 32;
    int tx = threadIdx.x, ty = threadIdx.y;
#pragma unroll
    for (int i = ty; i < 32; i += 8)
        t[i][tx] = s[(size_t)(h0 + i) * DIM + d0 + tx];
    __syncthreads();
#pragma unroll
    for (int i = ty; i < 32; i += 8) {
        float v = t[tx][i];
        g_W3[((size_t)e * DIM + d0 + i) * HID + h0 + tx] = __float2half_rn(v);
    }
}

// ---------------- GEMM1: stage = Ah, Al, B (3 tiles) ----------------
__device__ __forceinline__ void load_stage1(
    uint32_t st, int tid, int k0,
    const __half* Ah, const __half* Al, const __half* B)
{
#pragma unroll
    for (int rep = 0; rep < 4; rep++) {
        int c = tid + rep * 128;
        int row = c >> 2, kc = c & 3;
        uint32_t doff = row * ROWB + kc * 16;
        size_t goff = (size_t)row * DIM + k0 + kc * 8;
        cp16(st + doff,             Ah + goff);
        cp16(st + TILEB + doff,     Al + goff);
        cp16(st + 2 * TILEB + doff, B + goff);
    }
    CP_COMMIT();
}

__device__ __forceinline__ void compute_stage1(
    uint32_t st, int warpM, int warpN, int lane, float acc[4][8][4])
{
    int mlane = lane & 7;
    int mid = lane >> 3;
#pragma unroll
    for (int ks = 0; ks < 2; ks++) {
        uint32_t b[4][4];
#pragma unroll
        for (int nj = 0; nj < 4; nj++) {
            int row = warpN * 64 + nj * 16 + ((mid >> 1) << 3) + mlane;
            int colB = ks * 32 + ((mid & 1) << 4);
            ldsm4(b[nj], st + 2 * TILEB + row * ROWB + colB);
        }
#pragma unroll
        for (int mi = 0; mi < 4; mi++) {
            uint32_t ah[4], al[4];
            int row = warpM * 64 + mi * 16 + ((mid & 1) << 3) + mlane;
            int colB = ks * 32 + ((mid >> 1) << 4);
            ldsm4(ah, st + row * ROWB + colB);
            ldsm4(al, st + TILEB + row * ROWB + colB);
#pragma unroll
            for (int nj = 0; nj < 4; nj++)
#pragma unroll
                for (int tt = 0; tt < 2; tt++) {
                    int ni = nj * 2 + tt;
                    mma_hf32(acc[mi][ni], ah, b[nj][tt * 2], b[nj][tt * 2 + 1]);
                    mma_hf32(acc[mi][ni], al, b[nj][tt * 2], b[nj][tt * 2 + 1]);
                }
        }
    }
}

__global__ __launch_bounds__(128, 2) void k_gemm1() {
    int row0 = blockIdx.y * BM;
    int e = 0;
#pragma unroll
    for (int i = 1; i < NE; i++) if (g_off[i] <= row0) e = i;
    if (g_cnt[e] - (row0 - g_off[e]) <= 0) return;

    extern __shared__ __align__(128) char smem[];
    uint32_t sb = smem_u32(smem);
    int tid = threadIdx.x, wid = tid >> 5, lane = tid & 31;
    int warpM = wid >> 1, warpN = wid & 1;
    int n0 = blockIdx.x * BN;

    const __half* Ah = g_Xh + (size_t)row0 * DIM;
    const __half* Al = g_Xl + (size_t)row0 * DIM;
    const __half* Bp = g_Wc + (size_t)e * 2 * HID * DIM + (size_t)n0 * DIM;

    float acc[4][8][4];
#pragma unroll
    for (int a = 0; a < 4; a++)
#pragma unroll
        for (int b = 0; b < 8; b++)
#pragma unroll
            for (int c = 0; c < 4; c++) acc[a][b][c] = 0.0f;

    load_stage1(sb, tid, 0, Ah, Al, Bp);
    const int NC = DIM / BK;
    for (int c = 0; c < NC; c++) {
        CP_WAIT0();
        __syncthreads();
        if (c + 1 < NC)
            load_stage1(sb + ((c + 1) & 1) * STAGE1B, tid, (c + 1) * BK, Ah, Al, Bp);
        compute_stage1(sb + (c & 1) * STAGE1B, warpM, warpN, lane, acc);
    }

    // epilogue: SwiGLU -> single fp16, stage through smem, 16B stores
    __syncthreads();
    char* stg = smem + wid * 2048;        // 16 rows x 80B per warp region
    int qrow = lane >> 2, qcol = lane & 3;
    int jgb = (n0 >> 1) + warpN * 32;
#pragma unroll
    for (int mi = 0; mi < 4; mi++) {
        int r0 = row0 + warpM * 64 + mi * 16;
#pragma unroll
        for (int ni = 0; ni < 8; ni++) {
            int col = ni * 4 + qcol;
            float v0 = swishf(acc[mi][ni][0]) * acc[mi][ni][1];
            float v1 = swishf(acc[mi][ni][2]) * acc[mi][ni][3];
            *(__half*)(stg + qrow * 80 + col * 2) = __float2half_rn(v0);
            *(__half*)(stg + (qrow + 8) * 80 + col * 2) = __float2half_rn(v1);
        }
        __syncwarp();
#pragma unroll
        for (int k = 0; k < 2; k++) {
            int chunk = lane + 32 * k;            // 64 = 16 rows x 4 parts
            int row = chunk >> 2, part = chunk & 3;
            uint4 vh = *(uint4*)(stg + row * 80 + part * 16);
            size_t o = (size_t)(r0 + row) * HID + jgb + part * 8;
            *(uint4*)(g_S + o) = vh;
        }
        __syncwarp();
    }
}

// ---------------- GEMM2: stage = A, B (2 tiles), single mma ----------------
__device__ __forceinline__ void load_stage2(
    uint32_t st, int tid, int k0, const __half* A, const __half* B)
{
#pragma unroll
    for (int rep = 0; rep < 4; rep++) {
        int c = tid + rep * 128;
        int row = c >> 2, kc = c & 3;
        uint32_t doff = row * ROWB + kc * 16;
        size_t goff = (size_t)row * HID + k0 + kc * 8;
        cp16(st + doff,         A + goff);
        cp16(st + TILEB + doff, B + goff);
    }
    CP_COMMIT();
}

__device__ __forceinline__ void compute_stage2(
    uint32_t st, int warpM, int warpN, int lane, float acc[4][8][4])
{
    int mlane = lane & 7;
    int mid = lane >> 3;
#pragma unroll
    for (int ks = 0; ks < 2; ks++) {
        uint32_t b[4][4];
#pragma unroll
        for (int nj = 0; nj < 4; nj++) {
            int row = warpN * 64 + nj * 16 + ((mid >> 1) << 3) + mlane;
            int colB = ks * 32 + ((mid & 1) << 4);
            ldsm4(b[nj], st + TILEB + row * ROWB + colB);
        }
#pragma unroll
        for (int mi = 0; mi < 4; mi++) {
            uint32_t a[4];
            int row = warpM * 64 + mi * 16 + ((mid & 1) << 3) + mlane;
            int colB = ks * 32 + ((mid >> 1) << 4);
            ldsm4(a, st + row * ROWB + colB);
#pragma unroll
            for (int nj = 0; nj < 4; nj++)
#pragma unroll
                for (int tt = 0; tt < 2; tt++)
                    mma_hf32(acc[mi][nj * 2 + tt], a, b[nj][tt * 2], b[nj][tt * 2 + 1]);
        }
    }
}

__global__ __launch_bounds__(128, 2) void k_gemm2(float* __restrict__ out) {
    int row0 = blockIdx.y * BM;
    int e = 0;
#pragma unroll
    for (int i = 1; i < NE; i++) if (g_off[i] <= row0) e = i;
    if (g_cnt[e] - (row0 - g_off[e]) <= 0) return;

    extern __shared__ __align__(128) char smem[];
    uint32_t sb = smem_u32(smem);
    int tid = threadIdx.x, wid = tid >> 5, lane = tid & 31;
    int warpM = wid >> 1, warpN = wid & 1;
    int n0 = blockIdx.x * BN;

    const __half* Ap = g_S  + (size_t)row0 * HID;
    const __half* Bp = g_W3 + (size_t)e * DIM * HID + (size_t)n0 * HID;

    float acc[4][8][4];
#pragma unroll
    for (int a = 0; a < 4; a++)
#pragma unroll
        for (int b = 0; b < 8; b++)
#pragma unroll
            for (int c = 0; c < 4; c++) acc[a][b][c] = 0.0f;

    load_stage2(sb, tid, 0, Ap, Bp);
    const int NC = HID / BK;
    for (int c = 0; c < NC; c++) {
        CP_WAIT0();
        __syncthreads();
        if (c + 1 < NC)
            load_stage2(sb + ((c + 1) & 1) * STAGE2B, tid, (c + 1) * BK, Ap, Bp);
        compute_stage2(sb + (c & 1) * STAGE2B, warpM, warpN, lane, acc);
    }

    int qrow = lane >> 2, qcol = lane & 3;
#pragma unroll
    for (int mi = 0; mi < 4; mi++) {
        int rbase = row0 + warpM * 64 + mi * 16 + qrow;
#pragma unroll
        for (int half = 0; half < 2; half++) {
            int r = rbase + half * 8;
            int t = g_rowtok[r];
            if (t < 0) continue;
            float wgt = g_roww[r];
            float* orow = out + (size_t)t * DIM;
#pragma unroll
            for (int ni = 0; ni < 8; ni++) {
                int colg = n0 + warpN * 64 + ni * 8 + qcol * 2;
                redg_v2(orow + colg, wgt * acc[mi][ni][half * 2],
                                     wgt * acc[mi][ni][half * 2 + 1]);
            }
        }
    }
}

// ---------------- launch ----------------
extern "C" void kernel_launch(void* const* d_in, const int* in_sizes, int n_in,
                              void* d_out, int out_size) {
    const float* x  = (const float*)d_in[0];
    const float* Wg = (const float*)d_in[1];
    const float* W1 = (const float*)d_in[2];
    const float* W2 = (const float*)d_in[3];
    const float* W3 = (const float*)d_in[4];
    float* out = (float*)d_out;

    cudaFuncSetAttribute(k_gemm1, cudaFuncAttributeMaxDynamicSharedMemorySize, SMEM1SZ);
    cudaFuncSetAttribute(k_gemm2, cudaFuncAttributeMaxDynamicSharedMemorySize, SMEM2SZ);

    cudaMemsetAsync(out, 0, (size_t)T_TOK * DIM * sizeof(float));
    k_init<<<(RCAP + 255) / 256, 256>>>();
    k_gate<<<T_TOK / 8, 256>>>(x, Wg);
    k_offsets<<<1, 32>>>();
    k_scatter<<<(T_TOK * 2 + 255) / 256, 256>>>();
    k_gather<<<RCAP, 256>>>(x);
    k_tr12<<<dim3(HID / 32, DIM / 32, NE), dim3(32, 8)>>>(W1, 0);
    k_tr12<<<dim3(HID / 32, DIM / 32, NE), dim3(32, 8)>>>(W2, 1);
    k_tr3<<<dim3(DIM / 32, HID / 32, NE), dim3(32, 8)>>>(W3);

    k_gemm1<<<dim3(2 * HID / BN, RCAP / BM), 128, SMEM1SZ>>>();
    k_gemm2<<<dim3(DIM / BN, RCAP / BM), 128, SMEM2SZ>>>(out);
}

// round 11
// speedup vs baseline: 2.2684x; 1.4122x over previous
#include <cuda_runtime.h>
#include <cuda_fp16.h>
#include <cstdint>

#define T_TOK 8192
#define DIM   1024
#define HID   2048
#define NE    8
#define BM    128
#define BN    128
#define BK    32
#define RCAP  (T_TOK*2 + NE*128)   // 17408 rows = 136 tiles of 128

#define ROWB    80
#define TILEB   (128*ROWB)          // 10240 B
#define STAGEB  (2*TILEB)           // A, B = 20480 B
#define SMEMSZ  (2*STAGEB)          // 40960 B -> plenty for 2+ CTAs/SM

// ---------------- device scratch ----------------
__device__ int   g_cnt[NE], g_cur[NE], g_off[NE + 1];
__device__ int   g_tope[T_TOK * 2];
__device__ float g_topp[T_TOK * 2];
__device__ int   g_rowtok[RCAP];
__device__ float g_roww[RCAP];
__device__ __half g_X [(size_t)RCAP * DIM];           // single fp16
__device__ __half g_S [(size_t)RCAP * HID];           // single fp16
__device__ __half g_Wc[(size_t)NE * 2 * HID * DIM];   // [e][2h+p][d]
__device__ __half g_W3[(size_t)NE * DIM * HID];       // [e][d][h]

// ---------------- helpers ----------------
__device__ __forceinline__ uint32_t smem_u32(const void* p) {
    uint32_t a;
    asm("{ .reg .u64 t; cvta.to.shared.u64 t, %1; cvt.u32.u64 %0, t; }" : "=r"(a) : "l"(p));
    return a;
}
__device__ __forceinline__ void cp16(uint32_t dst, const void* src) {
    asm volatile("cp.async.cg.shared.global [%0], [%1], 16;" :: "r"(dst), "l"(src));
}
#define CP_COMMIT() asm volatile("cp.async.commit_group;" ::: "memory")
#define CP_WAIT0()  asm volatile("cp.async.wait_group 0;" ::: "memory")

__device__ __forceinline__ void ldsm4(uint32_t* r, uint32_t addr) {
    asm volatile("ldmatrix.sync.aligned.m8n8.x4.shared.b16 {%0,%1,%2,%3}, [%4];"
                 : "=r"(r[0]), "=r"(r[1]), "=r"(r[2]), "=r"(r[3]) : "r"(addr));
}
__device__ __forceinline__ void mma_hf32(float* c, const uint32_t* a, uint32_t b0, uint32_t b1) {
    asm volatile("mma.sync.aligned.m16n8k16.row.col.f32.f16.f16.f32 "
                 "{%0,%1,%2,%3}, {%4,%5,%6,%7}, {%8,%9}, {%0,%1,%2,%3};"
                 : "+f"(c[0]), "+f"(c[1]), "+f"(c[2]), "+f"(c[3])
                 : "r"(a[0]), "r"(a[1]), "r"(a[2]), "r"(a[3]), "r"(b0), "r"(b1));
}
__device__ __forceinline__ void redg_v2(float* p, float a, float b) {
    asm volatile("red.global.add.v2.f32 [%0], {%1, %2};" :: "l"(p), "f"(a), "f"(b) : "memory");
}
__device__ __forceinline__ float swishf(float a) { return a / (1.0f + __expf(-a)); }

// ---------------- routing kernels ----------------
__global__ void k_init() {
    int i = blockIdx.x * blockDim.x + threadIdx.x;
    if (i < NE) { g_cnt[i] = 0; g_cur[i] = 0; }
    if (i < RCAP) g_rowtok[i] = -1;
}

__global__ void k_gate(const float* __restrict__ x, const float* __restrict__ Wg) {
    __shared__ float sWgT[NE * DIM];
    for (int idx = threadIdx.x; idx < DIM * NE; idx += blockDim.x) {
        int d = idx >> 3, e = idx & 7;
        sWgT[e * DIM + d] = Wg[idx];
    }
    __syncthreads();
    int warp = threadIdx.x >> 5, lane = threadIdx.x & 31;
    int t = blockIdx.x * 8 + warp;
    const float* xr = x + (size_t)t * DIM;
    float acc[NE];
#pragma unroll
    for (int e = 0; e < NE; e++) acc[e] = 0.0f;
    for (int d = lane; d < DIM; d += 32) {
        float xv = xr[d];
#pragma unroll
        for (int e = 0; e < NE; e++) acc[e] += xv * sWgT[e * DIM + d];
    }
#pragma unroll
    for (int off = 16; off; off >>= 1)
#pragma unroll
        for (int e = 0; e < NE; e++) acc[e] += __shfl_xor_sync(0xffffffffu, acc[e], off);
    if (lane == 0) {
        int e0 = 0; float v0 = acc[0];
#pragma unroll
        for (int e = 1; e < NE; e++) if (acc[e] > v0) { v0 = acc[e]; e0 = e; }
        int e1 = -1; float v1 = -1e30f;
#pragma unroll
        for (int e = 0; e < NE; e++) if (e != e0 && acc[e] > v1) { v1 = acc[e]; e1 = e; }
        float ex = __expf(v1 - v0);
        g_tope[t * 2 + 0] = e0; g_topp[t * 2 + 0] = 1.0f / (1.0f + ex);
        g_tope[t * 2 + 1] = e1; g_topp[t * 2 + 1] = ex / (1.0f + ex);
        atomicAdd(&g_cnt[e0], 1);
        atomicAdd(&g_cnt[e1], 1);
    }
}

__global__ void k_offsets() {
    if (threadIdx.x == 0) {
        int o = 0;
#pragma unroll
        for (int e = 0; e < NE; e++) {
            g_off[e] = o;
            o += ((g_cnt[e] + 127) / 128) * 128;
        }
        g_off[NE] = o;
    }
}

__global__ void k_scatter() {
    int i = blockIdx.x * blockDim.x + threadIdx.x;
    if (i >= T_TOK * 2) return;
    int e = g_tope[i];
    int pos = g_off[e] + atomicAdd(&g_cur[e], 1);
    g_rowtok[pos] = i >> 1;
    g_roww[pos] = g_topp[i];
}

// gather X rows as single fp16
__global__ void k_gather(const float* __restrict__ x) {
    int r = blockIdx.x;
    int t = g_rowtok[r];
    int i = threadIdx.x;
    float4 v = make_float4(0.f, 0.f, 0.f, 0.f);
    if (t >= 0) v = ((const float4*)(x + (size_t)t * DIM))[i];
    __half2 a = __floats2half2_rn(v.x, v.y);
    __half2 b = __floats2half2_rn(v.z, v.w);
    *(uint2*)(g_X + (size_t)r * DIM + i * 4) =
        make_uint2(*(unsigned*)&a, *(unsigned*)&b);
}

// W1/W2 [e][d][h] -> Wc [e][2h+p][d] (single fp16), interleaved columns
__global__ void k_tr12(const float* __restrict__ src, int p) {
    __shared__ float t[32][33];
    int e = blockIdx.z;
    const float* s = src + (size_t)e * DIM * HID;
    int h0 = blockIdx.x * 32, d0 = blockIdx.y * 32;
    int tx = threadIdx.x, ty = threadIdx.y;
#pragma unroll
    for (int i = ty; i < 32; i += 8)
        t[i][tx] = s[(size_t)(d0 + i) * HID + h0 + tx];
    __syncthreads();
#pragma unroll
    for (int i = ty; i < 32; i += 8) {
        float v = t[tx][i];
        int n = 2 * (h0 + i) + p;
        g_Wc[((size_t)e * 2 * HID + n) * DIM + d0 + tx] = __float2half_rn(v);
    }
}

// W3 [e][h][d] -> W3T [e][d][h] (single fp16)
__global__ void k_tr3(const float* __restrict__ src) {
    __shared__ float t[32][33];
    int e = blockIdx.z;
    const float* s = src + (size_t)e * HID * DIM;
    int d0 = blockIdx.x * 32, h0 = blockIdx.y * 32;
    int tx = threadIdx.x, ty = threadIdx.y;
#pragma unroll
    for (int i = ty; i < 32; i += 8)
        t[i][tx] = s[(size_t)(h0 + i) * DIM + d0 + tx];
    __syncthreads();
#pragma unroll
    for (int i = ty; i < 32; i += 8) {
        float v = t[tx][i];
        g_W3[((size_t)e * DIM + d0 + i) * HID + h0 + tx] = __float2half_rn(v);
    }
}

// ---------------- shared GEMM machinery: stage = A, B (2 tiles) ----------------
__device__ __forceinline__ void load_stage(
    uint32_t st, int tid, int k0, int kstride, const __half* A, const __half* B)
{
#pragma unroll
    for (int rep = 0; rep < 4; rep++) {
        int c = tid + rep * 128;
        int row = c >> 2, kc = c & 3;
        uint32_t doff = row * ROWB + kc * 16;
        size_t goff = (size_t)row * kstride + k0 + kc * 8;
        cp16(st + doff,         A + goff);
        cp16(st + TILEB + doff, B + goff);
    }
    CP_COMMIT();
}

__device__ __forceinline__ void compute_stage(
    uint32_t st, int warpM, int warpN, int lane, float acc[4][8][4])
{
    int mlane = lane & 7;
    int mid = lane >> 3;
#pragma unroll
    for (int ks = 0; ks < 2; ks++) {
        uint32_t b[4][4];
#pragma unroll
        for (int nj = 0; nj < 4; nj++) {
            int row = warpN * 64 + nj * 16 + ((mid >> 1) << 3) + mlane;
            int colB = ks * 32 + ((mid & 1) << 4);
            ldsm4(b[nj], st + TILEB + row * ROWB + colB);
        }
#pragma unroll
        for (int mi = 0; mi < 4; mi++) {
            uint32_t a[4];
            int row = warpM * 64 + mi * 16 + ((mid & 1) << 3) + mlane;
            int colB = ks * 32 + ((mid >> 1) << 4);
            ldsm4(a, st + row * ROWB + colB);
#pragma unroll
            for (int nj = 0; nj < 4; nj++)
#pragma unroll
                for (int tt = 0; tt < 2; tt++)
                    mma_hf32(acc[mi][nj * 2 + tt], a, b[nj][tt * 2], b[nj][tt * 2 + 1]);
        }
    }
}

#define GEMM_MAINLOOP(NC, KSTRIDE)                                                  \
    load_stage(sb, tid, 0, KSTRIDE, Ap, Bp);                                        \
    for (int c = 0; c < (NC); c++) {                                                \
        CP_WAIT0();                                                                 \
        __syncthreads();                                                            \
        if (c + 1 < (NC))                                                           \
            load_stage(sb + ((c + 1) & 1) * STAGEB, tid, (c + 1) * BK, KSTRIDE,     \
                       Ap, Bp);                                                     \
        compute_stage(sb + (c & 1) * STAGEB, warpM, warpN, lane, acc);              \
    }

// ---------------- GEMM1: [RCAP,4096] = X @ Wc, epilogue SwiGLU -> S ----------------
__global__ __launch_bounds__(128, 2) void k_gemm1() {
    int row0 = blockIdx.y * BM;
    int e = 0;
#pragma unroll
    for (int i = 1; i < NE; i++) if (g_off[i] <= row0) e = i;
    if (g_cnt[e] - (row0 - g_off[e]) <= 0) return;

    extern __shared__ __align__(128) char smem[];
    uint32_t sb = smem_u32(smem);
    int tid = threadIdx.x, wid = tid >> 5, lane = tid & 31;
    int warpM = wid >> 1, warpN = wid & 1;
    int n0 = blockIdx.x * BN;

    const __half* Ap = g_X  + (size_t)row0 * DIM;
    const __half* Bp = g_Wc + (size_t)e * 2 * HID * DIM + (size_t)n0 * DIM;

    float acc[4][8][4];
#pragma unroll
    for (int a = 0; a < 4; a++)
#pragma unroll
        for (int b = 0; b < 8; b++)
#pragma unroll
            for (int c = 0; c < 4; c++) acc[a][b][c] = 0.0f;

    GEMM_MAINLOOP(DIM / BK, DIM)

    // epilogue: SwiGLU -> single fp16, stage through smem, 16B stores
    __syncthreads();
    char* stg = smem + wid * 2048;
    int qrow = lane >> 2, qcol = lane & 3;
    int jgb = (n0 >> 1) + warpN * 32;
#pragma unroll
    for (int mi = 0; mi < 4; mi++) {
        int r0 = row0 + warpM * 64 + mi * 16;
#pragma unroll
        for (int ni = 0; ni < 8; ni++) {
            int col = ni * 4 + qcol;
            float v0 = swishf(acc[mi][ni][0]) * acc[mi][ni][1];
            float v1 = swishf(acc[mi][ni][2]) * acc[mi][ni][3];
            *(__half*)(stg + qrow * 80 + col * 2) = __float2half_rn(v0);
            *(__half*)(stg + (qrow + 8) * 80 + col * 2) = __float2half_rn(v1);
        }
        __syncwarp();
#pragma unroll
        for (int k = 0; k < 2; k++) {
            int chunk = lane + 32 * k;            // 64 = 16 rows x 4 parts
            int row = chunk >> 2, part = chunk & 3;
            uint4 vh = *(uint4*)(stg + row * 80 + part * 16);
            size_t o = (size_t)(r0 + row) * HID + jgb + part * 8;
            *(uint4*)(g_S + o) = vh;
        }
        __syncwarp();
    }
}

// ---------------- GEMM2: out[t] += w * (S @ W3T) ----------------
__global__ __launch_bounds__(128, 2) void k_gemm2(float* __restrict__ out) {
    int row0 = blockIdx.y * BM;
    int e = 0;
#pragma unroll
    for (int i = 1; i < NE; i++) if (g_off[i] <= row0) e = i;
    if (g_cnt[e] - (row0 - g_off[e]) <= 0) return;

    extern __shared__ __align__(128) char smem[];
    uint32_t sb = smem_u32(smem);
    int tid = threadIdx.x, wid = tid >> 5, lane = tid & 31;
    int warpM = wid >> 1, warpN = wid & 1;
    int n0 = blockIdx.x * BN;

    const __half* Ap = g_S  + (size_t)row0 * HID;
    const __half* Bp = g_W3 + (size_t)e * DIM * HID + (size_t)n0 * HID;

    float acc[4][8][4];
#pragma unroll
    for (int a = 0; a < 4; a++)
#pragma unroll
        for (int b = 0; b < 8; b++)
#pragma unroll
            for (int c = 0; c < 4; c++) acc[a][b][c] = 0.0f;

    GEMM_MAINLOOP(HID / BK, HID)

    int qrow = lane >> 2, qcol = lane & 3;
#pragma unroll
    for (int mi = 0; mi < 4; mi++) {
        int rbase = row0 + warpM * 64 + mi * 16 + qrow;
#pragma unroll
        for (int half = 0; half < 2; half++) {
            int r = rbase + half * 8;
            int t = g_rowtok[r];
            if (t < 0) continue;
            float wgt = g_roww[r];
            float* orow = out + (size_t)t * DIM;
#pragma unroll
            for (int ni = 0; ni < 8; ni++) {
                int colg = n0 + warpN * 64 + ni * 8 + qcol * 2;
                redg_v2(orow + colg, wgt * acc[mi][ni][half * 2],
                                     wgt * acc[mi][ni][half * 2 + 1]);
            }
        }
    }
}

// ---------------- launch ----------------
extern "C" void kernel_launch(void* const* d_in, const int* in_sizes, int n_in,
                              void* d_out, int out_size) {
    const float* x  = (const float*)d_in[0];
    const float* Wg = (const float*)d_in[1];
    const float* W1 = (const float*)d_in[2];
    const float* W2 = (const float*)d_in[3];
    const float* W3 = (const float*)d_in[4];
    float* out = (float*)d_out;

    cudaFuncSetAttribute(k_gemm1, cudaFuncAttributeMaxDynamicSharedMemorySize, SMEMSZ);
    cudaFuncSetAttribute(k_gemm2, cudaFuncAttributeMaxDynamicSharedMemorySize, SMEMSZ);

    cudaMemsetAsync(out, 0, (size_t)T_TOK * DIM * sizeof(float));
    k_init<<<(RCAP + 255) / 256, 256>>>();
    k_gate<<<T_TOK / 8, 256>>>(x, Wg);
    k_offsets<<<1, 32>>>();
    k_scatter<<<(T_TOK * 2 + 255) / 256, 256>>>();
    k_gather<<<RCAP, 256>>>(x);
    k_tr12<<<dim3(HID / 32, DIM / 32, NE), dim3(32, 8)>>>(W1, 0);
    k_tr12<<<dim3(HID / 32, DIM / 32, NE), dim3(32, 8)>>>(W2, 1);
    k_tr3<<<dim3(DIM / 32, HID / 32, NE), dim3(32, 8)>>>(W3);

    k_gemm1<<<dim3(2 * HID / BN, RCAP / BM), 128, SMEMSZ>>>();
    k_gemm2<<<dim3(DIM / BN, RCAP / BM), 128, SMEMSZ>>>(out);
}

// round 12
// speedup vs baseline: 2.3459x; 1.0342x over previous
#include <cuda_runtime.h>
#include <cuda_fp16.h>
#include <cstdint>

#define T_TOK 8192
#define DIM   1024
#define HID   2048
#define NE    8
#define BM    128
#define BN    128
#define BK    32
#define RCAP  (T_TOK*2 + NE*128)   // 17408 rows = 136 tiles of 128

#define ROWB    80
#define TILEB   (128*ROWB)          // 10240 B
#define STAGEB  (2*TILEB)           // A, B = 20480 B
#define NSTAGE  3
#define SMEMSZ  (NSTAGE*STAGEB)     // 61440 B -> 2 CTAs/SM

// ---------------- device scratch ----------------
__device__ int   g_cnt[NE], g_cur[NE], g_off[NE + 1];
__device__ int   g_tope[T_TOK * 2];
__device__ float g_topp[T_TOK * 2];
__device__ int   g_rowtok[RCAP];
__device__ float g_roww[RCAP];
__device__ __half g_X [(size_t)RCAP * DIM];
__device__ __half g_S [(size_t)RCAP * HID];
__device__ __half g_Wc[(size_t)NE * 2 * HID * DIM];   // [e][2h+p][d]
__device__ __half g_W3[(size_t)NE * DIM * HID];       // [e][d][h]

// ---------------- helpers ----------------
__device__ __forceinline__ uint32_t smem_u32(const void* p) {
    uint32_t a;
    asm("{ .reg .u64 t; cvta.to.shared.u64 t, %1; cvt.u32.u64 %0, t; }" : "=r"(a) : "l"(p));
    return a;
}
__device__ __forceinline__ void cp16(uint32_t dst, const void* src) {
    asm volatile("cp.async.cg.shared.global [%0], [%1], 16;" :: "r"(dst), "l"(src));
}
#define CP_COMMIT() asm volatile("cp.async.commit_group;" ::: "memory")
#define CP_WAIT1()  asm volatile("cp.async.wait_group 1;" ::: "memory")
#define CP_WAIT0()  asm volatile("cp.async.wait_group 0;" ::: "memory")

__device__ __forceinline__ void ldsm4(uint32_t* r, uint32_t addr) {
    asm volatile("ldmatrix.sync.aligned.m8n8.x4.shared.b16 {%0,%1,%2,%3}, [%4];"
                 : "=r"(r[0]), "=r"(r[1]), "=r"(r[2]), "=r"(r[3]) : "r"(addr));
}
__device__ __forceinline__ void mma_hf32(float* c, const uint32_t* a, uint32_t b0, uint32_t b1) {
    asm volatile("mma.sync.aligned.m16n8k16.row.col.f32.f16.f16.f32 "
                 "{%0,%1,%2,%3}, {%4,%5,%6,%7}, {%8,%9}, {%0,%1,%2,%3};"
                 : "+f"(c[0]), "+f"(c[1]), "+f"(c[2]), "+f"(c[3])
                 : "r"(a[0]), "r"(a[1]), "r"(a[2]), "r"(a[3]), "r"(b0), "r"(b1));
}
__device__ __forceinline__ void redg_v2(float* p, float a, float b) {
    asm volatile("red.global.add.v2.f32 [%0], {%1, %2};" :: "l"(p), "f"(a), "f"(b) : "memory");
}
__device__ __forceinline__ float swishf(float a) { return a / (1.0f + __expf(-a)); }

// ---------------- routing kernels ----------------
__global__ void k_init() {
    int i = blockIdx.x * blockDim.x + threadIdx.x;
    if (i < NE) { g_cnt[i] = 0; g_cur[i] = 0; }
    if (i < RCAP) g_rowtok[i] = -1;
}

__global__ void k_gate(const float* __restrict__ x, const float* __restrict__ Wg) {
    __shared__ float sWgT[NE * DIM];
    for (int idx = threadIdx.x; idx < DIM * NE; idx += blockDim.x) {
        int d = idx >> 3, e = idx & 7;
        sWgT[e * DIM + d] = Wg[idx];
    }
    __syncthreads();
    int warp = threadIdx.x >> 5, lane = threadIdx.x & 31;
    int t = blockIdx.x * 8 + warp;
    const float* xr = x + (size_t)t * DIM;
    float acc[NE];
#pragma unroll
    for (int e = 0; e < NE; e++) acc[e] = 0.0f;
    for (int d = lane; d < DIM; d += 32) {
        float xv = xr[d];
#pragma unroll
        for (int e = 0; e < NE; e++) acc[e] += xv * sWgT[e * DIM + d];
    }
#pragma unroll
    for (int off = 16; off; off >>= 1)
#pragma unroll
        for (int e = 0; e < NE; e++) acc[e] += __shfl_xor_sync(0xffffffffu, acc[e], off);
    if (lane == 0) {
        int e0 = 0; float v0 = acc[0];
#pragma unroll
        for (int e = 1; e < NE; e++) if (acc[e] > v0) { v0 = acc[e]; e0 = e; }
        int e1 = -1; float v1 = -1e30f;
#pragma unroll
        for (int e = 0; e < NE; e++) if (e != e0 && acc[e] > v1) { v1 = acc[e]; e1 = e; }
        float ex = __expf(v1 - v0);
        g_tope[t * 2 + 0] = e0; g_topp[t * 2 + 0] = 1.0f / (1.0f + ex);
        g_tope[t * 2 + 1] = e1; g_topp[t * 2 + 1] = ex / (1.0f + ex);
        atomicAdd(&g_cnt[e0], 1);
        atomicAdd(&g_cnt[e1], 1);
    }
}

__global__ void k_offsets() {
    if (threadIdx.x == 0) {
        int o = 0;
#pragma unroll
        for (int e = 0; e < NE; e++) {
            g_off[e] = o;
            o += ((g_cnt[e] + 127) / 128) * 128;
        }
        g_off[NE] = o;
    }
}

__global__ void k_scatter() {
    int i = blockIdx.x * blockDim.x + threadIdx.x;
    if (i >= T_TOK * 2) return;
    int e = g_tope[i];
    int pos = g_off[e] + atomicAdd(&g_cur[e], 1);
    g_rowtok[pos] = i >> 1;
    g_roww[pos] = g_topp[i];
}

__global__ void k_gather(const float* __restrict__ x) {
    int r = blockIdx.x;
    int t = g_rowtok[r];
    int i = threadIdx.x;
    float4 v = make_float4(0.f, 0.f, 0.f, 0.f);
    if (t >= 0) v = ((const float4*)(x + (size_t)t * DIM))[i];
    __half2 a = __floats2half2_rn(v.x, v.y);
    __half2 b = __floats2half2_rn(v.z, v.w);
    *(uint2*)(g_X + (size_t)r * DIM + i * 4) =
        make_uint2(*(unsigned*)&a, *(unsigned*)&b);
}

// W1 and W2 [e][d][h] -> Wc [e][2h+p][d] (fp16), fused (p=0 for W1, p=1 for W2)
__global__ void k_tr12f(const float* __restrict__ W1, const float* __restrict__ W2) {
    __shared__ float t[32][33];
    int e = blockIdx.z;
    int h0 = blockIdx.x * 32, d0 = blockIdx.y * 32;
    int tx = threadIdx.x, ty = threadIdx.y;
#pragma unroll
    for (int p = 0; p < 2; p++) {
        const float* s = (p == 0 ? W1 : W2) + (size_t)e * DIM * HID;
        __syncthreads();
#pragma unroll
        for (int i = ty; i < 32; i += 8)
            t[i][tx] = s[(size_t)(d0 + i) * HID + h0 + tx];
        __syncthreads();
#pragma unroll
        for (int i = ty; i < 32; i += 8) {
            float v = t[tx][i];
            int n = 2 * (h0 + i) + p;
            g_Wc[((size_t)e * 2 * HID + n) * DIM + d0 + tx] = __float2half_rn(v);
        }
    }
}

// W3 [e][h][d] -> W3T [e][d][h] (single fp16)
__global__ void k_tr3(const float* __restrict__ src) {
    __shared__ float t[32][33];
    int e = blockIdx.z;
    const float* s = src + (size_t)e * HID * DIM;
    int d0 = blockIdx.x * 32, h0 = blockIdx.y * 32;
    int tx = threadIdx.x, ty = threadIdx.y;
#pragma unroll
    for (int i = ty; i < 32; i += 8)
        t[i][tx] = s[(size_t)(h0 + i) * DIM + d0 + tx];
    __syncthreads();
#pragma unroll
    for (int i = ty; i < 32; i += 8) {
        float v = t[tx][i];
        g_W3[((size_t)e * DIM + d0 + i) * HID + h0 + tx] = __float2half_rn(v);
    }
}

// ---------------- shared GEMM machinery: stage = A, B (2 tiles) ----------------
__device__ __forceinline__ void load_stage(
    uint32_t st, int tid, int k0, int kstride, const __half* A, const __half* B)
{
#pragma unroll
    for (int rep = 0; rep < 4; rep++) {
        int c = tid + rep * 128;
        int row = c >> 2, kc = c & 3;
        uint32_t doff = row * ROWB + kc * 16;
        size_t goff = (size_t)row * kstride + k0 + kc * 8;
        cp16(st + doff,         A + goff);
        cp16(st + TILEB + doff, B + goff);
    }
    CP_COMMIT();
}

__device__ __forceinline__ void compute_stage(
    uint32_t st, int warpM, int warpN, int lane, float acc[4][8][4])
{
    int mlane = lane & 7;
    int mid = lane >> 3;
#pragma unroll
    for (int ks = 0; ks < 2; ks++) {
        uint32_t b[4][4];
#pragma unroll
        for (int nj = 0; nj < 4; nj++) {
            int row = warpN * 64 + nj * 16 + ((mid >> 1) << 3) + mlane;
            int colB = ks * 32 + ((mid & 1) << 4);
            ldsm4(b[nj], st + TILEB + row * ROWB + colB);
        }
#pragma unroll
        for (int mi = 0; mi < 4; mi++) {
            uint32_t a[4];
            int row = warpM * 64 + mi * 16 + ((mid & 1) << 3) + mlane;
            int colB = ks * 32 + ((mid >> 1) << 4);
            ldsm4(a, st + row * ROWB + colB);
#pragma unroll
            for (int nj = 0; nj < 4; nj++)
#pragma unroll
                for (int tt = 0; tt < 2; tt++)
                    mma_hf32(acc[mi][nj * 2 + tt], a, b[nj][tt * 2], b[nj][tt * 2 + 1]);
        }
    }
}

// 3-stage pipeline: during compute(c), loads (c+1) and (c+2) are in flight.
// wait_group 1 guarantees load(c) complete while c+1 < NC; tail uses wait 0.
#define GEMM_MAINLOOP(NC, KSTRIDE)                                                  \
    load_stage(sb, tid, 0, KSTRIDE, Ap, Bp);                                        \
    load_stage(sb + STAGEB, tid, BK, KSTRIDE, Ap, Bp);                              \
    for (int c = 0; c < (NC); c++) {                                                \
        if (c + 1 < (NC)) { CP_WAIT1(); } else { CP_WAIT0(); }                      \
        __syncthreads();                                                            \
        if (c + 2 < (NC))                                                           \
            load_stage(sb + ((c + 2) % NSTAGE) * STAGEB, tid, (c + 2) * BK,         \
                       KSTRIDE, Ap, Bp);                                            \
        compute_stage(sb + (c % NSTAGE) * STAGEB, warpM, warpN, lane, acc);         \
    }

// ---------------- GEMM1: [RCAP,4096] = X @ Wc, epilogue SwiGLU -> S ----------------
__global__ __launch_bounds__(128, 2) void k_gemm1() {
    int row0 = blockIdx.y * BM;
    int e = 0;
#pragma unroll
    for (int i = 1; i < NE; i++) if (g_off[i] <= row0) e = i;
    if (g_cnt[e] - (row0 - g_off[e]) <= 0) return;

    extern __shared__ __align__(128) char smem[];
    uint32_t sb = smem_u32(smem);
    int tid = threadIdx.x, wid = tid >> 5, lane = tid & 31;
    int warpM = wid >> 1, warpN = wid & 1;
    int n0 = blockIdx.x * BN;

    const __half* Ap = g_X  + (size_t)row0 * DIM;
    const __half* Bp = g_Wc + (size_t)e * 2 * HID * DIM + (size_t)n0 * DIM;

    float acc[4][8][4];
#pragma unroll
    for (int a = 0; a < 4; a++)
#pragma unroll
        for (int b = 0; b < 8; b++)
#pragma unroll
            for (int c = 0; c < 4; c++) acc[a][b][c] = 0.0f;

    GEMM_MAINLOOP(DIM / BK, DIM)

    // epilogue: SwiGLU -> single fp16, stage through smem, 16B stores
    __syncthreads();
    char* stg = smem + wid * 2048;
    int qrow = lane >> 2, qcol = lane & 3;
    int jgb = (n0 >> 1) + warpN * 32;
#pragma unroll
    for (int mi = 0; mi < 4; mi++) {
        int r0 = row0 + warpM * 64 + mi * 16;
#pragma unroll
        for (int ni = 0; ni < 8; ni++) {
            int col = ni * 4 + qcol;
            float v0 = swishf(acc[mi][ni][0]) * acc[mi][ni][1];
            float v1 = swishf(acc[mi][ni][2]) * acc[mi][ni][3];
            *(__half*)(stg + qrow * 80 + col * 2) = __float2half_rn(v0);
            *(__half*)(stg + (qrow + 8) * 80 + col * 2) = __float2half_rn(v1);
        }
        __syncwarp();
#pragma unroll
        for (int k = 0; k < 2; k++) {
            int chunk = lane + 32 * k;
            int row = chunk >> 2, part = chunk & 3;
            uint4 vh = *(uint4*)(stg + row * 80 + part * 16);
            size_t o = (size_t)(r0 + row) * HID + jgb + part * 8;
            *(uint4*)(g_S + o) = vh;
        }
        __syncwarp();
    }
}

// ---------------- GEMM2: out[t] += w * (S @ W3T) ----------------
__global__ __launch_bounds__(128, 2) void k_gemm2(float* __restrict__ out) {
    int row0 = blockIdx.y * BM;
    int e = 0;
#pragma unroll
    for (int i = 1; i < NE; i++) if (g_off[i] <= row0) e = i;
    if (g_cnt[e] - (row0 - g_off[e]) <= 0) return;

    extern __shared__ __align__(128) char smem[];
    uint32_t sb = smem_u32(smem);
    int tid = threadIdx.x, wid = tid >> 5, lane = tid & 31;
    int warpM = wid >> 1, warpN = wid & 1;
    int n0 = blockIdx.x * BN;

    const __half* Ap = g_S  + (size_t)row0 * HID;
    const __half* Bp = g_W3 + (size_t)e * DIM * HID + (size_t)n0 * HID;

    float acc[4][8][4];
#pragma unroll
    for (int a = 0; a < 4; a++)
#pragma unroll
        for (int b = 0; b < 8; b++)
#pragma unroll
            for (int c = 0; c < 4; c++) acc[a][b][c] = 0.0f;

    GEMM_MAINLOOP(HID / BK, HID)

    int qrow = lane >> 2, qcol = lane & 3;
#pragma unroll
    for (int mi = 0; mi < 4; mi++) {
        int rbase = row0 + warpM * 64 + mi * 16 + qrow;
#pragma unroll
        for (int half = 0; half < 2; half++) {
            int r = rbase + half * 8;
            int t = g_rowtok[r];
            if (t < 0) continue;
            float wgt = g_roww[r];
            float* orow = out + (size_t)t * DIM;
#pragma unroll
            for (int ni = 0; ni < 8; ni++) {
                int colg = n0 + warpN * 64 + ni * 8 + qcol * 2;
                redg_v2(orow + colg, wgt * acc[mi][ni][half * 2],
                                     wgt * acc[mi][ni][half * 2 + 1]);
            }
        }
    }
}

// ---------------- launch ----------------
extern "C" void kernel_launch(void* const* d_in, const int* in_sizes, int n_in,
                              void* d_out, int out_size) {
    const float* x  = (const float*)d_in[0];
    const float* Wg = (const float*)d_in[1];
    const float* W1 = (const float*)d_in[2];
    const float* W2 = (const float*)d_in[3];
    const float* W3 = (const float*)d_in[4];
    float* out = (float*)d_out;

    cudaFuncSetAttribute(k_gemm1, cudaFuncAttributeMaxDynamicSharedMemorySize, SMEMSZ);
    cudaFuncSetAttribute(k_gemm2, cudaFuncAttributeMaxDynamicSharedMemorySize, SMEMSZ);

    cudaMemsetAsync(out, 0, (size_t)T_TOK * DIM * sizeof(float));
    k_init<<<(RCAP + 255) / 256, 256>>>();
    k_gate<<<T_TOK / 8, 256>>>(x, Wg);
    k_offsets<<<1, 32>>>();
    k_scatter<<<(T_TOK * 2 + 255) / 256, 256>>>();
    k_gather<<<RCAP, 256>>>(x);
    k_tr12f<<<dim3(HID / 32, DIM / 32, NE), dim3(32, 8)>>>(W1, W2);
    k_tr3<<<dim3(DIM / 32, HID / 32, NE), dim3(32, 8)>>>(W3);

    k_gemm1<<<dim3(2 * HID / BN, RCAP / BM), 128, SMEMSZ>>>();
    k_gemm2<<<dim3(DIM / BN, RCAP / BM), 128, SMEMSZ>>>(out);
}